// round 4
// baseline (speedup 1.0000x reference)
#include <cuda_runtime.h>
#include <cstdint>

// ============================ problem dims ============================
#define M_TOTAL 8192   // 4 * 2048 tokens
#define K_DIM   2048
#define H_DIM   8192

// ============================ scratch (device globals; no allocs) ============================
__device__ __align__(128) float g_xr  [(size_t)M_TOTAL * K_DIM];   // x rounded to tf32
__device__ __align__(128) float g_wgr [(size_t)H_DIM   * K_DIM];   // w_gate rounded
__device__ __align__(128) float g_wur [(size_t)H_DIM   * K_DIM];   // w_up rounded
__device__ __align__(128) float g_wdr [(size_t)K_DIM   * H_DIM];   // w_down rounded
__device__ __align__(128) float g_gate[(size_t)M_TOTAL * H_DIM];   // gate; reused as hidden
__device__ __align__(128) float g_up  [(size_t)M_TOTAL * H_DIM];   // up

// ============================ helpers (all plain sm_80+ PTX; no "a" features) ============================
__device__ __forceinline__ uint32_t smem_u32(const void* p) {
    uint32_t a;
    asm("{ .reg .u64 t; cvta.to.shared.u64 t, %1; cvt.u32.u64 %0, t; }" : "=r"(a) : "l"(p));
    return a;
}
__device__ __forceinline__ float rna_tf32(float x) {
    float r; asm("cvt.rna.tf32.f32 %0, %1;" : "=f"(r) : "f"(x)); return r;
}
#define CP_ASYNC16(saddr, gptr) \
    asm volatile("cp.async.cg.shared.global [%0], [%1], 16;" :: "r"(saddr), "l"(gptr))
#define CP_COMMIT() asm volatile("cp.async.commit_group;" ::: "memory")
#define CP_WAIT(n)  asm volatile("cp.async.wait_group %0;" :: "n"(n) : "memory")

__device__ __forceinline__ void mma_m16n8k8(float* c, const uint32_t* a, const uint32_t* b) {
    asm volatile(
        "mma.sync.aligned.m16n8k8.row.col.f32.tf32.tf32.f32 "
        "{%0,%1,%2,%3}, {%4,%5,%6,%7}, {%8,%9}, {%0,%1,%2,%3};"
        : "+f"(c[0]), "+f"(c[1]), "+f"(c[2]), "+f"(c[3])
        : "r"(a[0]), "r"(a[1]), "r"(a[2]), "r"(a[3]), "r"(b[0]), "r"(b[1]));
}

// ============================ tiling ============================
static constexpr int BM = 128, BN = 128, BK = 32;
static constexpr int LDP = 36;                      // padded row stride (floats): conflict-free frags
static constexpr int STAGES = 3;
static constexpr int STAGE_FLOATS = 2 * BM * LDP;   // A tile + B tile = 9216 floats
static constexpr int SMEM_BYTES = STAGES * STAGE_FLOATS * 4;  // 110592 B -> 2 CTAs/SM

// ============================ GEMM: C[M,N] = A[M,K] * B[N,K]^T (all row-major, fp32/tf32) ====
__global__ void __launch_bounds__(256, 2) gemm_tf32(
    const float* __restrict__ A, const float* __restrict__ B, float* __restrict__ C,
    int N, int K) {
    extern __shared__ float smem[];
    const uint32_t sb = smem_u32(smem);

    const int tid  = threadIdx.x;
    const int warp = tid >> 5, lane = tid & 31;
    const int warpM = warp >> 2, warpN = warp & 3;     // 2 x 4 warp grid
    const int g = lane >> 2, t = lane & 3;             // groupID, thread-in-group
    const int m0 = blockIdx.y * BM, n0 = blockIdx.x * BN;

    // cp.async load map: 256 threads, 16B each, 4 rounds per 128x32 tile
    const int ldr = tid >> 3;              // row 0..31 (+32*i)
    const int ldc = (tid & 7) * 4;         // col in floats (0,4,...,28)

    const int KT = K / BK;

    auto load_stage = [&](int s, int kk) {
        const size_t kb = (size_t)kk * BK + ldc;
        const float* ga = A + (size_t)(m0 + ldr) * K + kb;
        const float* gb = B + (size_t)(n0 + ldr) * K + kb;
        uint32_t sa = sb + (uint32_t)(s * STAGE_FLOATS + ldr * LDP + ldc) * 4;
        uint32_t sbB = sa + (uint32_t)(BM * LDP) * 4;
        #pragma unroll
        for (int i = 0; i < 4; i++) {
            CP_ASYNC16(sa,  ga);
            CP_ASYNC16(sbB, gb);
            ga += (size_t)32 * K;  gb += (size_t)32 * K;
            sa += 32 * LDP * 4;    sbB += 32 * LDP * 4;
        }
        CP_COMMIT();
    };

    float acc[4][4][4];
    #pragma unroll
    for (int mt = 0; mt < 4; mt++)
        #pragma unroll
        for (int nt = 0; nt < 4; nt++)
            #pragma unroll
            for (int j = 0; j < 4; j++) acc[mt][nt][j] = 0.0f;

    // prologue: stages 0..STAGES-2
    for (int s = 0; s < STAGES - 1; s++) load_stage(s, s);

    for (int i = 0; i < KT; i++) {
        CP_WAIT(STAGES - 2);
        __syncthreads();

        const int nk = i + STAGES - 1;
        if (nk < KT) load_stage(nk % STAGES, nk);
        else         CP_COMMIT();            // keep group count in lockstep

        const float* As = smem + (i % STAGES) * STAGE_FLOATS;
        const float* Bs = As + BM * LDP;

        #pragma unroll
        for (int ks = 0; ks < 4; ks++) {
            const int kc = ks * 8 + t;
            uint32_t af[4][4], bf[4][2];
            #pragma unroll
            for (int mt = 0; mt < 4; mt++) {
                const int r = warpM * 64 + mt * 16 + g;
                af[mt][0] = __float_as_uint(As[(r    ) * LDP + kc    ]);
                af[mt][1] = __float_as_uint(As[(r + 8) * LDP + kc    ]);
                af[mt][2] = __float_as_uint(As[(r    ) * LDP + kc + 4]);
                af[mt][3] = __float_as_uint(As[(r + 8) * LDP + kc + 4]);
            }
            #pragma unroll
            for (int nt = 0; nt < 4; nt++) {
                const int n = warpN * 32 + nt * 8 + g;
                bf[nt][0] = __float_as_uint(Bs[n * LDP + kc    ]);
                bf[nt][1] = __float_as_uint(Bs[n * LDP + kc + 4]);
            }
            #pragma unroll
            for (int mt = 0; mt < 4; mt++)
                #pragma unroll
                for (int nt = 0; nt < 4; nt++)
                    mma_m16n8k8(acc[mt][nt], af[mt], bf[nt]);
        }
        __syncthreads();
    }

    // epilogue: direct global stores (float2, 8B aligned)
    #pragma unroll
    for (int mt = 0; mt < 4; mt++) {
        const int row = m0 + warpM * 64 + mt * 16 + g;
        #pragma unroll
        for (int nt = 0; nt < 4; nt++) {
            const int col = n0 + warpN * 32 + nt * 8 + 2 * t;
            float2* p0 = reinterpret_cast<float2*>(C + (size_t)row * N + col);
            float2* p1 = reinterpret_cast<float2*>(C + (size_t)(row + 8) * N + col);
            *p0 = make_float2(acc[mt][nt][0], acc[mt][nt][1]);
            *p1 = make_float2(acc[mt][nt][2], acc[mt][nt][3]);
        }
    }
}

// ============================ elementwise kernels ============================
__global__ void __launch_bounds__(256) round_tf32_kernel(const float4* __restrict__ src,
                                                         float4* __restrict__ dst, int n4) {
    int i = blockIdx.x * blockDim.x + threadIdx.x;
    int stride = gridDim.x * blockDim.x;
    for (; i < n4; i += stride) {
        float4 v = src[i];
        v.x = rna_tf32(v.x); v.y = rna_tf32(v.y);
        v.z = rna_tf32(v.z); v.w = rna_tf32(v.w);
        dst[i] = v;
    }
}

// hid = rna_tf32( silu(gate) * up ), written in-place over gate
__global__ void __launch_bounds__(256) swiglu_kernel(float4* __restrict__ gate,
                                                     const float4* __restrict__ up, int n4) {
    int i = blockIdx.x * blockDim.x + threadIdx.x;
    int stride = gridDim.x * blockDim.x;
    for (; i < n4; i += stride) {
        float4 gv = gate[i], uv = up[i];
        float4 o;
        o.x = rna_tf32(gv.x * uv.x / (1.0f + __expf(-gv.x)));
        o.y = rna_tf32(gv.y * uv.y / (1.0f + __expf(-gv.y)));
        o.z = rna_tf32(gv.z * uv.z / (1.0f + __expf(-gv.z)));
        o.w = rna_tf32(gv.w * uv.w / (1.0f + __expf(-gv.w)));
        gate[i] = o;
    }
}

// ============================ host side ============================
extern "C" void kernel_launch(void* const* d_in, const int* in_sizes, int n_in,
                              void* d_out, int out_size) {
    const float* x  = (const float*)d_in[0];
    const float* wg = (const float*)d_in[1];
    const float* wu = (const float*)d_in[2];
    const float* wd = (const float*)d_in[3];
    float* out = (float*)d_out;

    void *p_xr, *p_wgr, *p_wur, *p_wdr, *p_gate, *p_up;
    cudaGetSymbolAddress(&p_xr,   g_xr);
    cudaGetSymbolAddress(&p_wgr,  g_wgr);
    cudaGetSymbolAddress(&p_wur,  g_wur);
    cudaGetSymbolAddress(&p_wdr,  g_wdr);
    cudaGetSymbolAddress(&p_gate, g_gate);
    cudaGetSymbolAddress(&p_up,   g_up);

    cudaFuncSetAttribute(gemm_tf32, cudaFuncAttributeMaxDynamicSharedMemorySize, SMEM_BYTES);

    // 1) pre-round all operands to tf32 (kills MMA truncation bias)
    const int n4_in = (M_TOTAL * K_DIM) / 4;   // x, wg, wu, wd all same element count
    round_tf32_kernel<<<2048, 256>>>((const float4*)x,  (float4*)p_xr,  n4_in);
    round_tf32_kernel<<<2048, 256>>>((const float4*)wg, (float4*)p_wgr, n4_in);
    round_tf32_kernel<<<2048, 256>>>((const float4*)wu, (float4*)p_wur, n4_in);
    round_tf32_kernel<<<2048, 256>>>((const float4*)wd, (float4*)p_wdr, n4_in);

    // 2) gate = x @ Wg^T ; up = x @ Wu^T   (M=8192, N=8192, K=2048)
    dim3 grid1(H_DIM / BN, M_TOTAL / BM);
    gemm_tf32<<<grid1, 256, SMEM_BYTES>>>((const float*)p_xr, (const float*)p_wgr,
                                          (float*)p_gate, H_DIM, K_DIM);
    gemm_tf32<<<grid1, 256, SMEM_BYTES>>>((const float*)p_xr, (const float*)p_wur,
                                          (float*)p_up, H_DIM, K_DIM);

    // 3) hidden = silu(gate)*up (in-place over gate), re-rounded to tf32
    const int n4_h = (M_TOTAL * H_DIM) / 4;
    swiglu_kernel<<<2048, 256>>>((float4*)p_gate, (const float4*)p_up, n4_h);

    // 4) out = hidden @ Wd^T   (M=8192, N=2048, K=8192)
    dim3 grid2(K_DIM / BN, M_TOTAL / BM);
    gemm_tf32<<<grid2, 256, SMEM_BYTES>>>((const float*)p_gate, (const float*)p_wdr,
                                          out, K_DIM, H_DIM);
}

// round 5
// speedup vs baseline: 1.9956x; 1.9956x over previous
#include <cuda_runtime.h>
#include <cuda_fp16.h>
#include <cstdint>

// ============================ problem dims ============================
#define M_TOTAL 8192   // 4 * 2048 tokens
#define K_DIM   2048
#define H_DIM   8192

// ============================ scratch (device globals; no allocs) ============================
__device__ __align__(128) __half g_xh [(size_t)M_TOTAL * K_DIM];   // x  -> fp16
__device__ __align__(128) __half g_wgh[(size_t)H_DIM   * K_DIM];   // w_gate -> fp16
__device__ __align__(128) __half g_wuh[(size_t)H_DIM   * K_DIM];   // w_up   -> fp16
__device__ __align__(128) __half g_wdh[(size_t)K_DIM   * H_DIM];   // w_down -> fp16
__device__ __align__(128) __half g_hid[(size_t)M_TOTAL * H_DIM];   // silu(g)*u in fp16

// ============================ helpers (plain sm_80+ PTX only) ============================
__device__ __forceinline__ uint32_t smem_u32(const void* p) {
    uint32_t a;
    asm("{ .reg .u64 t; cvta.to.shared.u64 t, %1; cvt.u32.u64 %0, t; }" : "=r"(a) : "l"(p));
    return a;
}
#define CP_ASYNC16(saddr, gptr) \
    asm volatile("cp.async.cg.shared.global [%0], [%1], 16;" :: "r"(saddr), "l"(gptr))
#define CP_COMMIT() asm volatile("cp.async.commit_group;" ::: "memory")
#define CP_WAIT(n)  asm volatile("cp.async.wait_group %0;" :: "n"(n) : "memory")

#define LDMATRIX_X4(R0, R1, R2, R3, addr) \
    asm volatile("ldmatrix.sync.aligned.m8n8.x4.shared.b16 {%0,%1,%2,%3}, [%4];" \
        : "=r"(R0), "=r"(R1), "=r"(R2), "=r"(R3) : "r"(addr))

__device__ __forceinline__ void mma_f16(float* c, const uint32_t* a, const uint32_t* b) {
    asm volatile(
        "mma.sync.aligned.m16n8k16.row.col.f32.f16.f16.f32 "
        "{%0,%1,%2,%3}, {%4,%5,%6,%7}, {%8,%9}, {%0,%1,%2,%3};"
        : "+f"(c[0]), "+f"(c[1]), "+f"(c[2]), "+f"(c[3])
        : "r"(a[0]), "r"(a[1]), "r"(a[2]), "r"(a[3]), "r"(b[0]), "r"(b[1]));
}

// ============================ tiling ============================
// Smem row = 32 halves (64B of data) stored at 80B stride.
// 80 = 5*16 -> ldmatrix's 8 rows per phase land on 8 distinct 16B bank groups.
static constexpr int ROW_STRIDE_B = 80;
static constexpr int BK = 32;                         // k-halves per stage
static constexpr int STAGE_ROWS  = 256;               // 128 A rows + 128 B rows
static constexpr int STAGE_BYTES = STAGE_ROWS * ROW_STRIDE_B;   // 20480
static constexpr int STAGES = 4;
static constexpr int SMEM_BYTES = STAGES * STAGE_BYTES;          // 81920 -> 2 CTAs/SM

// ============================ kernel 1: fused gate/up GEMM + SwiGLU ============================
// grid: (H/64, M/128). CTA computes gate[128x64] and up[128x64] sharing the A tile,
// applies silu(g)*u in registers, stores fp16 hidden. 8 warps: warpM in {0,1} (64 rows),
// warpN in {0..3} (16 cols each). Per-warp tile 64x16 for gate AND up.
__global__ void __launch_bounds__(256, 2) gemm_gateup(
    const __half* __restrict__ X, const __half* __restrict__ Wg,
    const __half* __restrict__ Wu, __half* __restrict__ Hid) {
    extern __shared__ char smem[];
    const uint32_t sb = smem_u32(smem);

    const int tid = threadIdx.x;
    const int warp = tid >> 5, lane = tid & 31;
    const int warpM = warp >> 2, warpN = warp & 3;
    const int m0 = blockIdx.y * 128, n0 = blockIdx.x * 64;

    const int r  = tid >> 2;          // 0..63
    const int ch = tid & 3;           // 16B chunk in row

    const int KT = K_DIM / BK;        // 64

    auto load_stage = [&](int s, int kk) {
        const size_t kb = (size_t)kk * BK + ch * 8;      // in halves
        const uint32_t sd = sb + (uint32_t)(s * STAGE_BYTES + r * ROW_STRIDE_B + ch * 16);
        CP_ASYNC16(sd,                       X  + (size_t)(m0 + r)      * K_DIM + kb);
        CP_ASYNC16(sd +  64 * ROW_STRIDE_B,  X  + (size_t)(m0 + 64 + r) * K_DIM + kb);
        CP_ASYNC16(sd + 128 * ROW_STRIDE_B,  Wg + (size_t)(n0 + r)      * K_DIM + kb);
        CP_ASYNC16(sd + 192 * ROW_STRIDE_B,  Wu + (size_t)(n0 + r)      * K_DIM + kb);
        CP_COMMIT();
    };

    float accg[4][2][4], accu[4][2][4];
    #pragma unroll
    for (int mt = 0; mt < 4; mt++)
        #pragma unroll
        for (int nt = 0; nt < 2; nt++)
            #pragma unroll
            for (int j = 0; j < 4; j++) { accg[mt][nt][j] = 0.f; accu[mt][nt][j] = 0.f; }

    for (int s = 0; s < STAGES - 1; s++) load_stage(s, s);

    // lane-dependent ldmatrix address pieces (bytes)
    const uint32_t a_lo = (uint32_t)((lane & 15) * ROW_STRIDE_B + (lane >> 4) * 16);
    const uint32_t b_lo = (uint32_t)(((lane & 7) + ((lane >> 4) << 3)) * ROW_STRIDE_B
                                     + (((lane >> 3) & 1) << 4));

    for (int i = 0; i < KT; i++) {
        CP_WAIT(2);
        __syncthreads();
        const int nk = i + STAGES - 1;
        if (nk < KT) load_stage(nk & (STAGES - 1), nk);
        else         CP_COMMIT();

        const uint32_t st = sb + (uint32_t)((i & (STAGES - 1)) * STAGE_BYTES);
        #pragma unroll
        for (int ks = 0; ks < 2; ks++) {
            const uint32_t kB = (uint32_t)(ks * 32);   // 16 halves = 32 bytes
            uint32_t a[4][4], bg[4], bu[4];
            #pragma unroll
            for (int mt = 0; mt < 4; mt++) {
                const uint32_t addr = st + (uint32_t)((warpM * 64 + mt * 16) * ROW_STRIDE_B)
                                        + a_lo + kB;
                LDMATRIX_X4(a[mt][0], a[mt][1], a[mt][2], a[mt][3], addr);
            }
            {
                const uint32_t addr = st + (uint32_t)((128 + warpN * 16) * ROW_STRIDE_B)
                                        + b_lo + kB;
                LDMATRIX_X4(bg[0], bg[1], bg[2], bg[3], addr);
                LDMATRIX_X4(bu[0], bu[1], bu[2], bu[3], addr + 64 * ROW_STRIDE_B);
            }
            #pragma unroll
            for (int mt = 0; mt < 4; mt++) {
                mma_f16(accg[mt][0], a[mt], bg + 0);
                mma_f16(accg[mt][1], a[mt], bg + 2);
                mma_f16(accu[mt][0], a[mt], bu + 0);
                mma_f16(accu[mt][1], a[mt], bu + 2);
            }
        }
        __syncthreads();
    }

    // epilogue: hid = silu(g) * u, fp16 pair stores (4B, contiguous halves)
    const int g4 = lane >> 2, t4 = lane & 3;
    #pragma unroll
    for (int mt = 0; mt < 4; mt++) {
        const int row = m0 + warpM * 64 + mt * 16 + g4;
        #pragma unroll
        for (int nt = 0; nt < 2; nt++) {
            const int col = n0 + warpN * 16 + nt * 8 + 2 * t4;
            #pragma unroll
            for (int h = 0; h < 2; h++) {   // h=0 -> c0,c1 @ row; h=1 -> c2,c3 @ row+8
                const float gx = accg[mt][nt][2 * h],     ux = accu[mt][nt][2 * h];
                const float gy = accg[mt][nt][2 * h + 1], uy = accu[mt][nt][2 * h + 1];
                const float vx = gx * ux / (1.0f + __expf(-gx));
                const float vy = gy * uy / (1.0f + __expf(-gy));
                *reinterpret_cast<__half2*>(Hid + (size_t)(row + 8 * h) * H_DIM + col) =
                    __floats2half2_rn(vx, vy);
            }
        }
    }
}

// ============================ kernel 2: down GEMM (fp16 in, fp32 out) ============================
// grid: (2048/128, M/128). C[M,2048] = Hid[M,8192] * Wd[2048,8192]^T.
__global__ void __launch_bounds__(256, 2) gemm_down(
    const __half* __restrict__ A, const __half* __restrict__ B, float* __restrict__ C) {
    extern __shared__ char smem[];
    const uint32_t sb = smem_u32(smem);

    const int tid = threadIdx.x;
    const int warp = tid >> 5, lane = tid & 31;
    const int warpM = warp >> 2, warpN = warp & 3;   // warp tile 64x32
    const int m0 = blockIdx.y * 128, n0 = blockIdx.x * 128;

    const int r  = tid >> 2;
    const int ch = tid & 3;

    const int KT = H_DIM / BK;        // 256

    auto load_stage = [&](int s, int kk) {
        const size_t kb = (size_t)kk * BK + ch * 8;
        const uint32_t sd = sb + (uint32_t)(s * STAGE_BYTES + r * ROW_STRIDE_B + ch * 16);
        CP_ASYNC16(sd,                       A + (size_t)(m0 + r)      * H_DIM + kb);
        CP_ASYNC16(sd +  64 * ROW_STRIDE_B,  A + (size_t)(m0 + 64 + r) * H_DIM + kb);
        CP_ASYNC16(sd + 128 * ROW_STRIDE_B,  B + (size_t)(n0 + r)      * H_DIM + kb);
        CP_ASYNC16(sd + 192 * ROW_STRIDE_B,  B + (size_t)(n0 + 64 + r) * H_DIM + kb);
        CP_COMMIT();
    };

    float acc[4][4][4];
    #pragma unroll
    for (int mt = 0; mt < 4; mt++)
        #pragma unroll
        for (int nt = 0; nt < 4; nt++)
            #pragma unroll
            for (int j = 0; j < 4; j++) acc[mt][nt][j] = 0.f;

    for (int s = 0; s < STAGES - 1; s++) load_stage(s, s);

    const uint32_t a_lo = (uint32_t)((lane & 15) * ROW_STRIDE_B + (lane >> 4) * 16);
    const uint32_t b_lo = (uint32_t)(((lane & 7) + ((lane >> 4) << 3)) * ROW_STRIDE_B
                                     + (((lane >> 3) & 1) << 4));

    for (int i = 0; i < KT; i++) {
        CP_WAIT(2);
        __syncthreads();
        const int nk = i + STAGES - 1;
        if (nk < KT) load_stage(nk & (STAGES - 1), nk);
        else         CP_COMMIT();

        const uint32_t st = sb + (uint32_t)((i & (STAGES - 1)) * STAGE_BYTES);
        #pragma unroll
        for (int ks = 0; ks < 2; ks++) {
            const uint32_t kB = (uint32_t)(ks * 32);
            uint32_t a[4][4], b[8];
            #pragma unroll
            for (int mt = 0; mt < 4; mt++) {
                const uint32_t addr = st + (uint32_t)((warpM * 64 + mt * 16) * ROW_STRIDE_B)
                                        + a_lo + kB;
                LDMATRIX_X4(a[mt][0], a[mt][1], a[mt][2], a[mt][3], addr);
            }
            {
                const uint32_t addr = st + (uint32_t)((128 + warpN * 32) * ROW_STRIDE_B)
                                        + b_lo + kB;
                LDMATRIX_X4(b[0], b[1], b[2], b[3], addr);
                LDMATRIX_X4(b[4], b[5], b[6], b[7], addr + 16 * ROW_STRIDE_B);
            }
            #pragma unroll
            for (int mt = 0; mt < 4; mt++)
                #pragma unroll
                for (int nt = 0; nt < 4; nt++)
                    mma_f16(acc[mt][nt], a[mt], b + 2 * nt);
        }
        __syncthreads();
    }

    const int g4 = lane >> 2, t4 = lane & 3;
    #pragma unroll
    for (int mt = 0; mt < 4; mt++) {
        const int row = m0 + warpM * 64 + mt * 16 + g4;
        #pragma unroll
        for (int nt = 0; nt < 4; nt++) {
            const int col = n0 + warpN * 32 + nt * 8 + 2 * t4;
            *reinterpret_cast<float2*>(C + (size_t)row * K_DIM + col) =
                make_float2(acc[mt][nt][0], acc[mt][nt][1]);
            *reinterpret_cast<float2*>(C + (size_t)(row + 8) * K_DIM + col) =
                make_float2(acc[mt][nt][2], acc[mt][nt][3]);
        }
    }
}

// ============================ conversion kernel ============================
__global__ void __launch_bounds__(256) f32_to_f16_kernel(const float4* __restrict__ src,
                                                         uint2* __restrict__ dst, int n4) {
    int i = blockIdx.x * blockDim.x + threadIdx.x;
    const int stride = gridDim.x * blockDim.x;
    for (; i < n4; i += stride) {
        const float4 v = src[i];
        const __half2 h0 = __floats2half2_rn(v.x, v.y);
        const __half2 h1 = __floats2half2_rn(v.z, v.w);
        uint2 o;
        o.x = *reinterpret_cast<const uint32_t*>(&h0);
        o.y = *reinterpret_cast<const uint32_t*>(&h1);
        dst[i] = o;
    }
}

// ============================ host side ============================
extern "C" void kernel_launch(void* const* d_in, const int* in_sizes, int n_in,
                              void* d_out, int out_size) {
    const float* x  = (const float*)d_in[0];
    const float* wg = (const float*)d_in[1];
    const float* wu = (const float*)d_in[2];
    const float* wd = (const float*)d_in[3];
    float* out = (float*)d_out;

    void *p_xh, *p_wgh, *p_wuh, *p_wdh, *p_hid;
    cudaGetSymbolAddress(&p_xh,  g_xh);
    cudaGetSymbolAddress(&p_wgh, g_wgh);
    cudaGetSymbolAddress(&p_wuh, g_wuh);
    cudaGetSymbolAddress(&p_wdh, g_wdh);
    cudaGetSymbolAddress(&p_hid, g_hid);

    cudaFuncSetAttribute(gemm_gateup, cudaFuncAttributeMaxDynamicSharedMemorySize, SMEM_BYTES);
    cudaFuncSetAttribute(gemm_down,   cudaFuncAttributeMaxDynamicSharedMemorySize, SMEM_BYTES);

    // 1) fp32 -> fp16 (rn; same 10-bit mantissa as tf32 -> same error class)
    const int n4 = (M_TOTAL * K_DIM) / 4;   // all four inputs have equal element counts
    f32_to_f16_kernel<<<2048, 256>>>((const float4*)x,  (uint2*)p_xh,  n4);
    f32_to_f16_kernel<<<2048, 256>>>((const float4*)wg, (uint2*)p_wgh, n4);
    f32_to_f16_kernel<<<2048, 256>>>((const float4*)wu, (uint2*)p_wuh, n4);
    f32_to_f16_kernel<<<2048, 256>>>((const float4*)wd, (uint2*)p_wdh, n4);

    // 2) fused gate/up + SwiGLU -> fp16 hidden
    gemm_gateup<<<dim3(H_DIM / 64, M_TOTAL / 128), 256, SMEM_BYTES>>>(
        (const __half*)p_xh, (const __half*)p_wgh, (const __half*)p_wuh, (__half*)p_hid);

    // 3) down GEMM -> fp32 out
    gemm_down<<<dim3(K_DIM / 128, M_TOTAL / 128), 256, SMEM_BYTES>>>(
        (const __half*)p_hid, (const __half*)p_wdh, out);
}